// round 9
// baseline (speedup 1.0000x reference)
#include <cuda_runtime.h>
#include <math.h>

// Problem constants
#define BB   2
#define SS_  4096
#define DD   512
#define HH   8
#define DEP  64
#define BH   16
#define MM   8192

// Scratch
__device__ float g_qh[BH * SS_ * DEP];   // [bh][s][d], tf32 bits, d perm'd per 8
__device__ float g_kh[BH * SS_ * DEP];   // [bh][s][d], tf32 bits, d perm'd per 8
__device__ float g_vh[BH * SS_ * DEP];   // [bh][d][s] TRANSPOSED, tf32 bits, s perm'd per 8
__device__ float g_ctx[MM * DD];
__device__ float g_inv[BH * SS_];

__device__ __forceinline__ unsigned f2tf(float x) {
    unsigned u;
    asm("cvt.rna.tf32.f32 %0, %1;" : "=r"(u) : "f"(x));
    return u;
}

// 3-bit rotate-left: position of original index j in permuted storage.
// Stored order = [0,4,1,5,2,6,3,7]  =>  uint2 at 2t yields (t, t+4).
__device__ __forceinline__ int rot3(int j) { return ((j << 1) | (j >> 2)) & 7; }

__device__ __forceinline__ void mma_tf32(float* d, const unsigned* a, const unsigned* b) {
    asm volatile(
        "mma.sync.aligned.m16n8k8.row.col.f32.tf32.tf32.f32 "
        "{%0,%1,%2,%3}, {%4,%5,%6,%7}, {%8,%9}, {%0,%1,%2,%3};"
        : "+f"(d[0]), "+f"(d[1]), "+f"(d[2]), "+f"(d[3])
        : "r"(a[0]), "r"(a[1]), "r"(a[2]), "r"(a[3]), "r"(b[0]), "r"(b[1]));
}

__device__ __forceinline__ void cp16(void* smem_ptr, const void* gptr) {
    unsigned s = (unsigned)__cvta_generic_to_shared(smem_ptr);
    asm volatile("cp.async.cg.shared.global [%0], [%1], 16;" :: "r"(s), "l"(gptr));
}
#define CP_COMMIT() asm volatile("cp.async.commit_group;" ::: "memory")
#define CP_WAIT0()  asm volatile("cp.async.wait_group 0;" ::: "memory")

// ---------------------------------------------------------------------------
// Projection GEMM: Y(8192x512) = X @ W + bias, tf32 MMA, cp.async pipelined.
// MODE 0: row-major fp32 out.
// MODE 1: head-split, tf32 bits, d permuted per 8-chunk (Q, K).
// MODE 2: head-split TRANSPOSED [bh][d][s], tf32 bits, s permuted per 8 (V).
// smem: fp32 staging, double buffered. cvt on the register path (same bits).
// ---------------------------------------------------------------------------
template <int MODE>
__global__ void __launch_bounds__(256, 2)
gemm512_mma(const float* __restrict__ X, const float* __restrict__ W,
            const float* __restrict__ bias, float* __restrict__ Y) {
    extern __shared__ float psm[];
    float* Xb[2] = {psm, psm + 4608};            // [m][k] stride 36
    float* Wb[2] = {psm + 9216, psm + 13568};    // [k][n] stride 136

    const int tid = threadIdx.x;
    const int lane = tid & 31, w = tid >> 5;
    const int g = lane >> 2, t = lane & 3;
    const int wm = w & 3, wn = w >> 2;
    const int m0 = blockIdx.y * 128, n0 = blockIdx.x * 128;

    float acc[2][8][4];
#pragma unroll
    for (int mt = 0; mt < 2; mt++)
#pragma unroll
        for (int nt = 0; nt < 8; nt++)
#pragma unroll
            for (int c = 0; c < 4; c++) acc[mt][nt][c] = 0.f;

    const int xr = tid >> 1, xk = (tid & 1) * 16;
    const int wr = tid >> 3, wc = (tid & 7) * 16;

    // prologue: tile 0
#pragma unroll
    for (int i = 0; i < 4; i++) {
        cp16(&Xb[0][xr * 36 + xk + i * 4], &X[(size_t)(m0 + xr) * 512 + xk + i * 4]);
        cp16(&Wb[0][wr * 136 + wc + i * 4], &W[(size_t)wr * 512 + n0 + wc + i * 4]);
    }
    CP_COMMIT();
    CP_WAIT0();
    __syncthreads();

    for (int it = 0; it < 16; it++) {
        if (it < 15) {
            const int k0 = (it + 1) * 32;
            float* Xn = Xb[(it + 1) & 1];
            float* Wn = Wb[(it + 1) & 1];
#pragma unroll
            for (int i = 0; i < 4; i++) {
                cp16(&Xn[xr * 36 + xk + i * 4], &X[(size_t)(m0 + xr) * 512 + k0 + xk + i * 4]);
                cp16(&Wn[wr * 136 + wc + i * 4], &W[(size_t)(k0 + wr) * 512 + n0 + wc + i * 4]);
            }
            CP_COMMIT();
        }
        const float* Xs = Xb[it & 1];
        const float* Ws = Wb[it & 1];
#pragma unroll
        for (int ks = 0; ks < 4; ks++) {
            const int kk = ks * 8;
            unsigned a[2][4];
#pragma unroll
            for (int mt = 0; mt < 2; mt++) {
                const int r0 = wm * 32 + mt * 16;
                a[mt][0] = f2tf(Xs[(r0 + g) * 36 + kk + t]);
                a[mt][1] = f2tf(Xs[(r0 + g + 8) * 36 + kk + t]);
                a[mt][2] = f2tf(Xs[(r0 + g) * 36 + kk + t + 4]);
                a[mt][3] = f2tf(Xs[(r0 + g + 8) * 36 + kk + t + 4]);
            }
#pragma unroll
            for (int nt = 0; nt < 8; nt++) {
                unsigned b[2];
                const int nn = wn * 64 + nt * 8 + g;
                b[0] = f2tf(Ws[(kk + t) * 136 + nn]);
                b[1] = f2tf(Ws[(kk + t + 4) * 136 + nn]);
                mma_tf32(acc[0][nt], a[0], b);
                mma_tf32(acc[1][nt], a[1], b);
            }
        }
        if (it < 15) {
            CP_WAIT0();
            __syncthreads();
        }
    }

#pragma unroll
    for (int nt = 0; nt < 8; nt++) {
        const int colg = n0 + wn * 64 + nt * 8 + 2 * t;
        const float b0 = bias[colg], b1 = bias[colg + 1];
#pragma unroll
        for (int mt = 0; mt < 2; mt++) {
            const int rbase = m0 + wm * 32 + mt * 16;
#pragma unroll
            for (int half = 0; half < 2; half++) {
                const int r = rbase + g + half * 8;
                float ox = acc[mt][nt][half * 2 + 0] + b0;
                float oy = acc[mt][nt][half * 2 + 1] + b1;
                if (MODE == 0) {
                    float2 o = make_float2(ox, oy);
                    *(float2*)&Y[(size_t)r * 512 + colg] = o;
                } else if (MODE == 1) {
                    const int b = r >> 12, s = r & 4095;
                    const int h = colg >> 6;
                    const int dbase = (colg & 63) & ~7;
                    const int j0 = colg & 7;  // = 2t
                    const size_t base = (((size_t)(b * 8 + h)) * SS_ + s) * DEP;
                    Y[base + dbase + rot3(j0)]     = __uint_as_float(f2tf(ox));
                    Y[base + dbase + rot3(j0 + 1)] = __uint_as_float(f2tf(oy));
                } else {
                    const int b = r >> 12, s = r & 4095;
                    const int sp = (s & ~7) | rot3(s & 7);
                    const int h = colg >> 6, d0 = colg & 63;
                    const size_t bh64 = (size_t)(b * 8 + h) * 64;
                    Y[(bh64 + d0)     * SS_ + sp] = __uint_as_float(f2tf(ox));
                    Y[(bh64 + d0 + 1) * SS_ + sp] = __uint_as_float(f2tf(oy));
                }
            }
        }
    }
}

// ---------------------------------------------------------------------------
// Causal flash-style attention, tf32 MMA, cp.async double-buffered K/V,
// one __syncthreads per iteration, paired LDS.64 fragment loads.
// smem (u32): Qs/Ps [128][72]=9216, Kb[2][64][72]=9216, Vb[2][64][72]=9216
//   total 27648 u32 = 110592 B
// ---------------------------------------------------------------------------
__global__ void __launch_bounds__(256, 2)
attn_kernel(float* __restrict__ attn_out, int write_attn) {
    extern __shared__ unsigned sm[];
    unsigned* Qs  = sm;                 // [row][d'] stride 72 (d perm'd), reused as Ps
    unsigned* Kb[2] = {sm + 9216,  sm + 13824};   // [j][d'] stride 72
    unsigned* Vb[2] = {sm + 18432, sm + 23040};   // [d][j'] stride 72 (j perm'd)

    const int tid = threadIdx.x;
    const int lane = tid & 31, w = tid >> 5;
    const int g = lane >> 2, t = lane & 3;
    const int rt = 31 - blockIdx.x;     // heavy blocks first
    const int bh = blockIdx.y;
    const int row0 = rt * 128;

    const float* __restrict__ Qh = g_qh + (size_t)bh * SS_ * DEP;
    const float* __restrict__ Kh = g_kh + (size_t)bh * SS_ * DEP;
    const float* __restrict__ Vh = g_vh + (size_t)bh * SS_ * DEP;  // [d][s]

    const int kvr = tid >> 2;            // 0..63
    const int kvc = (tid & 3) * 16;      // 0,16,32,48

    // Prologue: Q + K0 + V0 in one group
    {
        const int qr = tid >> 1, qc = (tid & 1) * 32;
#pragma unroll
        for (int i = 0; i < 8; i++)
            cp16(&Qs[qr * 72 + qc + i * 4], &Qh[(size_t)(row0 + qr) * DEP + qc + i * 4]);
    }
#pragma unroll
    for (int i = 0; i < 4; i++) {
        cp16(&Kb[0][kvr * 72 + kvc + i * 4], &Kh[(size_t)kvr * DEP + kvc + i * 4]);
        cp16(&Vb[0][kvr * 72 + kvc + i * 4], &Vh[(size_t)kvr * SS_ + kvc + i * 4]);
    }
    CP_COMMIT();
    CP_WAIT0();
    __syncthreads();

    // Extract Q fragments: paired uint2 loads (d-permuted layout)
    unsigned qa[8][4];
    {
        const int rq = w * 16;
#pragma unroll
        for (int ks = 0; ks < 8; ks++) {
            const int kk = ks * 8;
            uint2 lo = *(const uint2*)&Qs[(rq + g) * 72 + kk + 2 * t];
            uint2 hi = *(const uint2*)&Qs[(rq + g + 8) * 72 + kk + 2 * t];
            qa[ks][0] = lo.x; qa[ks][1] = hi.x; qa[ks][2] = lo.y; qa[ks][3] = hi.y;
        }
    }

    float ctx[8][4];
#pragma unroll
    for (int nt = 0; nt < 8; nt++)
#pragma unroll
        for (int c = 0; c < 4; c++) ctx[nt][c] = 0.f;
    float rs0 = 0.f, rs1 = 0.f;

    const int gi0 = row0 + w * 16 + g;
    const int gi1 = gi0 + 8;
    const int ctmax = 2 * rt + 1;

    for (int ct = 0; ct <= ctmax; ct++) {
        // Prefetch next tile (into buffer whose readers all passed last sync)
        if (ct < ctmax) {
            unsigned* Kn = Kb[(ct + 1) & 1];
            unsigned* Vn = Vb[(ct + 1) & 1];
            const size_t gk = (size_t)((ct + 1) * 64 + kvr) * DEP + kvc;
            const size_t gv = (size_t)kvr * SS_ + (ct + 1) * 64 + kvc;
#pragma unroll
            for (int i = 0; i < 4; i++) {
                cp16(&Kn[kvr * 72 + kvc + i * 4], &Kh[gk + i * 4]);
                cp16(&Vn[kvr * 72 + kvc + i * 4], &Vh[gv + i * 4]);
            }
            CP_COMMIT();
        }

        const unsigned* Ks = Kb[ct & 1];
        const unsigned* Vs = Vb[ct & 1];

        // GEMM1: S = Q K^T; B-frags as paired uint2 (d-permuted K)
        float s[8][4];
#pragma unroll
        for (int nt = 0; nt < 8; nt++)
#pragma unroll
            for (int c = 0; c < 4; c++) s[nt][c] = 0.f;
#pragma unroll
        for (int ks = 0; ks < 8; ks++) {
            const int kk = ks * 8;
#pragma unroll
            for (int nt = 0; nt < 8; nt++) {
                uint2 bu = *(const uint2*)&Ks[(nt * 8 + g) * 72 + kk + 2 * t];
                unsigned b[2] = {bu.x, bu.y};
                mma_tf32(s[nt], qa[ks], b);
            }
        }

        // exp + causal mask; streaming-write unnormalized P; stage tf32(P)
        unsigned* Ps = Qs;
#pragma unroll
        for (int nt = 0; nt < 8; nt++) {
            const int cj = ct * 64 + nt * 8 + 2 * t;
            float e00 = (cj     <= gi0) ? __expf(s[nt][0] * 0.125f) : 0.f;
            float e01 = (cj + 1 <= gi0) ? __expf(s[nt][1] * 0.125f) : 0.f;
            float e10 = (cj     <= gi1) ? __expf(s[nt][2] * 0.125f) : 0.f;
            float e11 = (cj + 1 <= gi1) ? __expf(s[nt][3] * 0.125f) : 0.f;
            rs0 += e00 + e01;
            rs1 += e10 + e11;
            if (write_attn) {
                __stcs((float2*)&attn_out[((size_t)bh * SS_ + gi0) * SS_ + cj],
                       make_float2(e00, e01));
                __stcs((float2*)&attn_out[((size_t)bh * SS_ + gi1) * SS_ + cj],
                       make_float2(e10, e11));
            }
            uint2 u0, u1;
            u0.x = f2tf(e00); u0.y = f2tf(e01);
            u1.x = f2tf(e10); u1.y = f2tf(e11);
            *(uint2*)&Ps[(w * 16 + g) * 72 + nt * 8 + 2 * t] = u0;
            *(uint2*)&Ps[(w * 16 + g + 8) * 72 + nt * 8 + 2 * t] = u1;
        }
        __syncwarp();

        // GEMM2: ctx += P V; B-frags paired uint2 (j-permuted V_T)
#pragma unroll
        for (int js = 0; js < 8; js++) {
            const int jj = js * 8;
            unsigned pa[4];
            pa[0] = Ps[(w * 16 + g) * 72 + jj + t];
            pa[1] = Ps[(w * 16 + g + 8) * 72 + jj + t];
            pa[2] = Ps[(w * 16 + g) * 72 + jj + t + 4];
            pa[3] = Ps[(w * 16 + g + 8) * 72 + jj + t + 4];
#pragma unroll
            for (int nt = 0; nt < 8; nt++) {
                uint2 bu = *(const uint2*)&Vs[(nt * 8 + g) * 72 + jj + 2 * t];
                unsigned b[2] = {bu.x, bu.y};
                mma_tf32(ctx[nt], pa, b);
            }
        }

        if (ct < ctmax) {
            CP_WAIT0();
            __syncthreads();
        }
    }

    // Row sums -> inv
    rs0 += __shfl_xor_sync(0xffffffffu, rs0, 1);
    rs0 += __shfl_xor_sync(0xffffffffu, rs0, 2);
    rs1 += __shfl_xor_sync(0xffffffffu, rs1, 1);
    rs1 += __shfl_xor_sync(0xffffffffu, rs1, 2);
    const float inv0 = 1.f / rs0, inv1 = 1.f / rs1;
    if (t == 0) {
        g_inv[(size_t)bh * SS_ + gi0] = inv0;
        g_inv[(size_t)bh * SS_ + gi1] = inv1;
    }

    // Store normalized ctx
    const int b = bh >> 3, h = bh & 7;
#pragma unroll
    for (int nt = 0; nt < 8; nt++) {
        const int d = nt * 8 + 2 * t;
        float2 o0, o1;
        o0.x = ctx[nt][0] * inv0; o0.y = ctx[nt][1] * inv0;
        o1.x = ctx[nt][2] * inv1; o1.y = ctx[nt][3] * inv1;
        *(float2*)&g_ctx[((size_t)(b * SS_ + gi0)) * DD + h * 64 + d] = o0;
        *(float2*)&g_ctx[((size_t)(b * SS_ + gi1)) * DD + h * 64 + d] = o1;
    }
}

// ---------------------------------------------------------------------------
// Normalize attn in place; zeros above diagonal (write-only there).
// ---------------------------------------------------------------------------
__global__ void __launch_bounds__(256)
normalize_attn(float* __restrict__ attn) {
    const size_t idx = (size_t)blockIdx.x * 256 + threadIdx.x;  // float4 index
    const int j4 = (int)(idx & 1023);
    const int i  = (int)((idx >> 10) & 4095);
    const int bh = (int)(idx >> 22);
    const int j  = j4 * 4;
    float4* p = (float4*)attn + idx;
    if (j > i) {
        __stcs(p, make_float4(0.f, 0.f, 0.f, 0.f));
    } else {
        const float inv = g_inv[(size_t)bh * SS_ + i];
        float4 v = __ldcs(p);
        if (j + 3 <= i) {
            v.x *= inv; v.y *= inv; v.z *= inv; v.w *= inv;
        } else {
            v.x = (j + 0 <= i) ? v.x * inv : 0.f;
            v.y = (j + 1 <= i) ? v.y * inv : 0.f;
            v.z = (j + 2 <= i) ? v.z * inv : 0.f;
            v.w = (j + 3 <= i) ? v.w * inv : 0.f;
        }
        __stcs(p, v);
    }
}

// ---------------------------------------------------------------------------
extern "C" void kernel_launch(void* const* d_in, const int* in_sizes, int n_in,
                              void* d_out, int out_size) {
    const float* q  = (const float*)d_in[2];
    const float* k  = (const float*)d_in[0];
    const float* v  = (const float*)d_in[1];
    const float* Wq = (const float*)d_in[4];
    const float* bq = (const float*)d_in[5];
    const float* Wk = (const float*)d_in[6];
    const float* bk = (const float*)d_in[7];
    const float* Wv = (const float*)d_in[8];
    const float* bv = (const float*)d_in[9];
    const float* Wo = (const float*)d_in[10];
    const float* bo = (const float*)d_in[11];

    float* out = (float*)d_out;
    const size_t BSD = (size_t)BB * SS_ * DD;
    const size_t ATT = (size_t)BH * SS_ * SS_;

    float* out_main = nullptr;
    float* attn_out = nullptr;
    if ((size_t)out_size >= BSD + ATT) {
        out_main = out;
        attn_out = out + BSD;
    } else if ((size_t)out_size >= ATT) {
        attn_out = out;
    } else {
        out_main = out;
    }

    void *pq, *pk, *pv, *pctx;
    cudaGetSymbolAddress(&pq, g_qh);
    cudaGetSymbolAddress(&pk, g_kh);
    cudaGetSymbolAddress(&pv, g_vh);
    cudaGetSymbolAddress(&pctx, g_ctx);

    cudaFuncSetAttribute(attn_kernel,
                         cudaFuncAttributeMaxDynamicSharedMemorySize, 110592);
    cudaFuncSetAttribute(gemm512_mma<0>,
                         cudaFuncAttributeMaxDynamicSharedMemorySize, 71680);
    cudaFuncSetAttribute(gemm512_mma<1>,
                         cudaFuncAttributeMaxDynamicSharedMemorySize, 71680);
    cudaFuncSetAttribute(gemm512_mma<2>,
                         cudaFuncAttributeMaxDynamicSharedMemorySize, 71680);

    dim3 ggrid(4, 64);
    gemm512_mma<1><<<ggrid, 256, 71680>>>(q, Wq, bq, (float*)pq);
    gemm512_mma<1><<<ggrid, 256, 71680>>>(k, Wk, bk, (float*)pk);
    gemm512_mma<2><<<ggrid, 256, 71680>>>(v, Wv, bv, (float*)pv);

    attn_kernel<<<dim3(32, BH), 256, 110592>>>(attn_out, attn_out != nullptr);

    if (attn_out) {
        normalize_attn<<<262144, 256>>>(attn_out);
    }
    if (out_main) {
        gemm512_mma<0><<<ggrid, 256, 71680>>>((const float*)pctx, Wo, bo, out_main);
    }
}